// round 9
// baseline (speedup 1.0000x reference)
#include <cuda_runtime.h>
#include <cstdint>

#define BATCH 16
#define HW    262144
#define NPIX  4194304

// ---------------- scratch (device globals; no runtime allocation) ----------
// q,k packed rows: per (b,h), 1024 floats = 32 groups x (16 hi | 16 lo), k-permuted
__device__ float g_qp[NPIX * 2], g_kp[NPIX * 2];
__device__ float g_vT[BATCH * 8 * HW];      // [B,C,W,H] (h k-permuted)
__device__ float g_attn[BATCH * HW];        // [B,H,H] (j k-permuted after softmax)

// ---------------- helpers ---------------------------------------------------
__device__ __forceinline__ float tf32r(float x) {
    uint32_t u; asm("cvt.rna.tf32.f32 %0, %1;" : "=r"(u) : "f"(x));
    return __uint_as_float(u);
}
__device__ __forceinline__ int kperm(int k) {
    return (k & ~15) | ((k & 3) << 2) | ((k >> 2) & 3);
}
#define CPA16(s, g)   asm volatile("cp.async.cg.shared.global [%0], [%1], 16;" :: "r"(s), "l"(g) : "memory")
#define CPA_COMMIT()  asm volatile("cp.async.commit_group;" ::: "memory")
#define CPA_WAIT(n)   asm volatile("cp.async.wait_group %0;" :: "n"(n) : "memory")

__device__ __forceinline__ uint32_t smem_u32(const void* p) {
    uint32_t a;
    asm("{ .reg .u64 t; cvta.to.shared.u64 t, %1; cvt.u32.u64 %0, t; }" : "=r"(a) : "l"(p));
    return a;
}
// chunk-level swizzle: row r (128B rows), 16B chunk ch (0..7).
// f depends only on r&7 -> rows differing by multiples of 8 share it.
__device__ __forceinline__ uint32_t swz128(int r, int ch) {
    const int f = ((r & 1) << 2) | ((r >> 1) & 3);
    return (uint32_t)(r * 128 + ((ch ^ f) << 4));
}
__device__ __forceinline__ uint4 lds128(uint32_t a) {
    uint4 v;
    asm volatile("ld.shared.v4.b32 {%0,%1,%2,%3}, [%4];"
                 : "=r"(v.x), "=r"(v.y), "=r"(v.z), "=r"(v.w) : "r"(a));
    return v;
}
#define MMA4(c, a0, a1, a2, a3, b0, b1) \
    asm volatile("mma.sync.aligned.m16n8k8.row.col.f32.tf32.tf32.f32 " \
                 "{%0,%1,%2,%3},{%4,%5,%6,%7},{%8,%9},{%0,%1,%2,%3};" \
                 : "+f"((c)[0]), "+f"((c)[1]), "+f"((c)[2]), "+f"((c)[3]) \
                 : "r"(a0), "r"(a1), "r"(a2), "r"(a3), "r"(b0), "r"(b1))

// ---------------------------------------------------------------------------
// Fused q/k/v 1x1 convs.  q,k written as packed hi/lo tf32 rows (1024 wide,
// k-permuted); v transposed to [B,C,W,H] (tf32, h k-permuted).
// ---------------------------------------------------------------------------
__global__ void __launch_bounds__(256)
qkv_kernel(const float* __restrict__ x,
           const float* __restrict__ Wq, const float* __restrict__ bq,
           const float* __restrict__ Wk, const float* __restrict__ bk,
           const float* __restrict__ Wv, const float* __restrict__ bv)
{
    __shared__ float sWq[8], sWk[8], sWv[64], sBv[8], sB2[2];
    __shared__ float sv[8][32][33];
    const int tid = threadIdx.x;
    if (tid < 8) { sWq[tid] = Wq[tid]; sWk[tid] = Wk[tid]; sBv[tid] = bv[tid]; }
    if (tid >= 8 && tid < 72) sWv[tid - 8] = Wv[tid - 8];
    if (tid == 72) sB2[0] = bq[0];
    if (tid == 73) sB2[1] = bk[0];
    __syncthreads();

    const int b = blockIdx.z, h0 = blockIdx.y * 32, w0 = blockIdx.x * 32;
    const int j = tid & 31, i0 = tid >> 5;

    for (int ii = 0; ii < 4; ii++) {
        const int i = i0 + ii * 8;
        const int h = h0 + i, w = w0 + j;
        const size_t pb = ((size_t)b * 8) * HW + (size_t)h * 512 + w;
        float xv[8];
#pragma unroll
        for (int c = 0; c < 8; c++) xv[c] = x[pb + (size_t)c * HW];

        float q = sB2[0], k = sB2[1];
#pragma unroll
        for (int c = 0; c < 8; c++) { q += xv[c] * sWq[c]; k += xv[c] * sWk[c]; }
        const int grp = w >> 4, pos = ((w & 3) << 2) | ((w >> 2) & 3);
        const size_t p = ((size_t)b * 512 + h) * 1024 + grp * 32 + pos;
        const float qh = tf32r(q), kh = tf32r(k);
        g_qp[p] = qh; g_qp[p + 16] = tf32r(q - qh);
        g_kp[p] = kh; g_kp[p + 16] = tf32r(k - kh);

#pragma unroll
        for (int o = 0; o < 8; o++) {
            float v = sBv[o];
#pragma unroll
            for (int c = 0; c < 8; c++) v += xv[c] * sWv[o * 8 + c];
            sv[o][i][j] = tf32r(v);
        }
    }
    __syncthreads();

    for (int ii = 0; ii < 4; ii++) {
        const int wl = i0 + ii * 8;
        const int hl = j;
#pragma unroll
        for (int c = 0; c < 8; c++) {
            g_vT[(((size_t)b * 8 + c) * 512 + (w0 + wl)) * 512 + kperm(h0 + hl)] = sv[c][hl][wl];
        }
    }
}

// ---------------------------------------------------------------------------
// GEMM1 (logits, 3xTF32): unchanged proven R8 shape.
// 256 threads, warp tile 32x64, packed hi/lo rows 1024 wide, 32 chunks of 16 k.
// ---------------------------------------------------------------------------
__global__ void __launch_bounds__(256, 2)
gemm_logits(const float* __restrict__ Ab, const float* __restrict__ Bb,
            float* __restrict__ Cb)
{
    constexpr int ROWLEN = 1024;
    constexpr int NCH    = 32;
    constexpr int STAGES = 3;
    constexpr uint32_t TA = 128 * 32 * 4;
    constexpr uint32_t SB = 2 * TA;

    extern __shared__ char smem[];
    const uint32_t s0 = smem_u32(smem);

    const int tid  = threadIdx.x;
    const int lane = tid & 31;
    const int wid  = tid >> 5;
    const int wm   = (wid & 3) * 32;
    const int wn   = (wid >> 2) * 64;
    const int gid  = lane >> 2;
    const int tig  = lane & 3;

    const int z = blockIdx.z;
    const size_t m0 = (size_t)blockIdx.y * 128;
    const size_t n0 = (size_t)blockIdx.x * 128;
    const float* A = Ab + (size_t)z * 512 * ROWLEN;
    const float* B = Bb + (size_t)z * 512 * ROWLEN;
    float* C = Cb + (size_t)z * HW;

    uint32_t bA[2], bB[2];
#pragma unroll
    for (int s = 0; s < 2; s++) {
        bA[s] = swz128(wm + gid, s * 4 + tig);
        bB[s] = TA + swz128(wn + gid, s * 4 + tig);
    }

    const int seg  = tid & 7;
    const int row0 = tid >> 3;
    const uint32_t lsw0 = swz128(row0, seg);
    const float* Arow = A + (m0 + row0) * ROWLEN + seg * 4;
    const float* Brow = B + (n0 + row0) * ROWLEN + seg * 4;

    auto load_chunk = [&](int c, uint32_t base) {
        const uint32_t sb = base + lsw0;
        const int go = c * 32;
#pragma unroll
        for (int i = 0; i < 4; i++) {
            CPA16(sb + i * 4096,      Arow + go + i * 32 * ROWLEN);
            CPA16(sb + TA + i * 4096, Brow + go + i * 32 * ROWLEN);
        }
    };

    float acc[2][8][4] = {};

    uint32_t stW = s0, stR = s0;
#pragma unroll
    for (int c = 0; c < STAGES - 1; c++) {
        load_chunk(c, stW); CPA_COMMIT();
        stW += SB; if (stW == s0 + STAGES * SB) stW = s0;
    }

    for (int c = 0; c < NCH; c++) {
        CPA_WAIT(STAGES - 2);
        __syncthreads();
        if (c + STAGES - 1 < NCH) load_chunk(c + STAGES - 1, stW);
        CPA_COMMIT();
        stW += SB; if (stW == s0 + STAGES * SB) stW = s0;

        const uint32_t sA = stR;
        stR += SB; if (stR == s0 + STAGES * SB) stR = s0;

        const uint32_t ahB = sA + bA[0], alB = sA + bA[1];
        const uint32_t bhB = sA + bB[0], blB = sA + bB[1];
        const uint4 h0 = lds128(ahB),        h1 = lds128(ahB + 1024);
        const uint4 h2 = lds128(ahB + 2048), h3 = lds128(ahB + 3072);
        const uint4 l0 = lds128(alB),        l1 = lds128(alB + 1024);
        const uint4 l2 = lds128(alB + 2048), l3 = lds128(alB + 3072);
#pragma unroll
        for (int nt = 0; nt < 8; nt++) {
            const uint4 bh = lds128(bhB + nt * 1024);
            const uint4 bl = lds128(blB + nt * 1024);
            MMA4(acc[0][nt], h0.x, h1.x, h0.y, h1.y, bh.x, bh.y);
            MMA4(acc[0][nt], l0.x, l1.x, l0.y, l1.y, bh.x, bh.y);
            MMA4(acc[0][nt], h0.x, h1.x, h0.y, h1.y, bl.x, bl.y);
            MMA4(acc[0][nt], h0.z, h1.z, h0.w, h1.w, bh.z, bh.w);
            MMA4(acc[0][nt], l0.z, l1.z, l0.w, l1.w, bh.z, bh.w);
            MMA4(acc[0][nt], h0.z, h1.z, h0.w, h1.w, bl.z, bl.w);
            MMA4(acc[1][nt], h2.x, h3.x, h2.y, h3.y, bh.x, bh.y);
            MMA4(acc[1][nt], l2.x, l3.x, l2.y, l3.y, bh.x, bh.y);
            MMA4(acc[1][nt], h2.x, h3.x, h2.y, h3.y, bl.x, bl.y);
            MMA4(acc[1][nt], h2.z, h3.z, h2.w, h3.w, bh.z, bh.w);
            MMA4(acc[1][nt], l2.z, l3.z, l2.w, l3.w, bh.z, bh.w);
            MMA4(acc[1][nt], h2.z, h3.z, h2.w, h3.w, bl.z, bl.w);
        }
    }

#pragma unroll
    for (int mt = 0; mt < 2; mt++) {
        const size_t r0 = m0 + wm + mt * 16 + gid;
#pragma unroll
        for (int nt = 0; nt < 8; nt++) {
            const size_t cc = n0 + wn + nt * 8 + tig * 2;
            *(float2*)(C + r0 * 512 + cc)       = make_float2(acc[mt][nt][0], acc[mt][nt][1]);
            *(float2*)(C + (r0 + 8) * 512 + cc) = make_float2(acc[mt][nt][2], acc[mt][nt][3]);
        }
    }
}

// ---------------------------------------------------------------------------
// GEMM2 (out = attn @ vT): 128 threads, 4 warps in 2x2, warp tile 64x64.
// CTA 128x128, K-chunk 32, 3-stage cp.async, 96KB smem -> 2 CTAs/SM.
// 32 LDS.128 per 128 HMMA per warp-chunk (0.25 LDS/MMA).
// ---------------------------------------------------------------------------
__global__ void __launch_bounds__(128, 2)
gemm_out(const float* __restrict__ Ab, const float* __restrict__ Bb,
         float* __restrict__ Cb)
{
    constexpr int STAGES = 3;
    constexpr uint32_t TA = 128 * 32 * 4;   // 16 KB
    constexpr uint32_t SB = 2 * TA;         // 32 KB

    extern __shared__ char smem[];
    const uint32_t s0 = smem_u32(smem);

    const int tid  = threadIdx.x;
    const int lane = tid & 31;
    const int wid  = tid >> 5;
    const int wm   = (wid & 1) * 64;
    const int wn   = (wid >> 1) * 64;
    const int gid  = lane >> 2;
    const int tig  = lane & 3;

    const int z = blockIdx.z;
    const size_t m0 = (size_t)blockIdx.y * 128;
    const size_t n0 = (size_t)blockIdx.x * 128;
    const float* A = Ab + (size_t)(z >> 3) * HW;   // attn shared across 8 channels
    const float* B = Bb + (size_t)z * HW;
    float* C = Cb + (size_t)z * HW;

    uint32_t bA[2], bB[2];
#pragma unroll
    for (int s = 0; s < 2; s++) {
        bA[s] = swz128(wm + gid, s * 4 + tig);
        bB[s] = TA + swz128(wn + gid, s * 4 + tig);
    }

    // loader: 128 threads -> (seg 0..7) x (row0 0..15), 8 rows (+16 apart) each tile
    const int seg  = tid & 7;
    const int row0 = tid >> 3;
    const uint32_t lsw0 = swz128(row0, seg);           // +i*2048 for row0+i*16
    const float* Arow = A + (m0 + row0) * 512 + seg * 4;
    const float* Brow = B + (n0 + row0) * 512 + seg * 4;

    auto load_chunk = [&](int c, uint32_t base) {
        const uint32_t sb = base + lsw0;
        const int go = c * 32;
#pragma unroll
        for (int i = 0; i < 8; i++) {
            CPA16(sb + i * 2048,      Arow + go + i * 16 * 512);
            CPA16(sb + TA + i * 2048, Brow + go + i * 16 * 512);
        }
    };

    float acc[4][8][4] = {};

    uint32_t stW = s0, stR = s0;
#pragma unroll
    for (int c = 0; c < STAGES - 1; c++) {
        load_chunk(c, stW); CPA_COMMIT();
        stW += SB; if (stW == s0 + STAGES * SB) stW = s0;
    }

    for (int c = 0; c < 16; c++) {
        CPA_WAIT(STAGES - 2);
        __syncthreads();
        if (c + STAGES - 1 < 16) load_chunk(c + STAGES - 1, stW);
        CPA_COMMIT();
        stW += SB; if (stW == s0 + STAGES * SB) stW = s0;

        const uint32_t sA = stR;
        stR += SB; if (stR == s0 + STAGES * SB) stR = s0;

#pragma unroll
        for (int g = 0; g < 2; g++) {
            const uint32_t aB  = sA + bA[g];
            const uint32_t bBs = sA + bB[g];
            uint4 a[8];
#pragma unroll
            for (int i = 0; i < 8; i++) a[i] = lds128(aB + i * 1024);
#pragma unroll
            for (int nt = 0; nt < 8; nt++) {
                const uint4 bv = lds128(bBs + nt * 1024);
#pragma unroll
                for (int mt = 0; mt < 4; mt++) {
                    MMA4(acc[mt][nt], a[2*mt].x, a[2*mt+1].x, a[2*mt].y, a[2*mt+1].y, bv.x, bv.y);
                    MMA4(acc[mt][nt], a[2*mt].z, a[2*mt+1].z, a[2*mt].w, a[2*mt+1].w, bv.z, bv.w);
                }
            }
        }
    }

#pragma unroll
    for (int mt = 0; mt < 4; mt++) {
        const size_t r0 = m0 + wm + mt * 16 + gid;
#pragma unroll
        for (int nt = 0; nt < 8; nt++) {
            const size_t cc = n0 + wn + nt * 8 + tig * 2;
            *(float2*)(C + r0 * 512 + cc)       = make_float2(acc[mt][nt][0], acc[mt][nt][1]);
            *(float2*)(C + (r0 + 8) * 512 + cc) = make_float2(acc[mt][nt][2], acc[mt][nt][3]);
        }
    }
}

// ---------------------------------------------------------------------------
// Row softmax over g_attn; reads natural order, writes k-permuted + tf32.
// ---------------------------------------------------------------------------
__global__ void softmax_kernel()
{
    const int row = blockIdx.x;
    const int tid = threadIdx.x;
    float* rp = g_attn + (size_t)row * 512;

    float4 v = *(float4*)(rp + tid * 4);
    float m = fmaxf(fmaxf(v.x, v.y), fmaxf(v.z, v.w));
#pragma unroll
    for (int o = 16; o > 0; o >>= 1) m = fmaxf(m, __shfl_xor_sync(0xFFFFFFFFu, m, o));

    __shared__ float sred[4];
    const int wid = tid >> 5, lane = tid & 31;
    if (lane == 0) sred[wid] = m;
    __syncthreads();
    m = fmaxf(fmaxf(sred[0], sred[1]), fmaxf(sred[2], sred[3]));
    __syncthreads();

    v.x = __expf(v.x - m); v.y = __expf(v.y - m);
    v.z = __expf(v.z - m); v.w = __expf(v.w - m);
    float s = v.x + v.y + v.z + v.w;
#pragma unroll
    for (int o = 16; o > 0; o >>= 1) s += __shfl_xor_sync(0xFFFFFFFFu, s, o);
    if (lane == 0) sred[wid] = s;
    __syncthreads();
    s = sred[0] + sred[1] + sred[2] + sred[3];

    const float inv = 1.0f / s;
    const int G = tid >> 2, u = tid & 3;
    float* gp = rp + G * 16 + u;
    __syncthreads();
    gp[0]  = tf32r(v.x * inv);
    gp[4]  = tf32r(v.y * inv);
    gp[8]  = tf32r(v.z * inv);
    gp[12] = tf32r(v.w * inv);
}

// ---------------------------------------------------------------------------
extern "C" void kernel_launch(void* const* d_in, const int* in_sizes, int n_in,
                              void* d_out, int out_size)
{
    const float* x  = (const float*)d_in[0];
    const float* Wq = (const float*)d_in[1];
    const float* bq = (const float*)d_in[2];
    const float* Wk = (const float*)d_in[3];
    const float* bk = (const float*)d_in[4];
    const float* Wv = (const float*)d_in[5];
    const float* bv = (const float*)d_in[6];
    float* out = (float*)d_out;

    float *pqp, *pkp, *pvT, *pattn;
    cudaGetSymbolAddress((void**)&pqp,  g_qp);
    cudaGetSymbolAddress((void**)&pkp,  g_kp);
    cudaGetSymbolAddress((void**)&pvT,  g_vT);
    cudaGetSymbolAddress((void**)&pattn, g_attn);

    const int SMEM_G = 3 * 2 * 16384;   // 96 KB
    cudaFuncSetAttribute(gemm_logits, cudaFuncAttributeMaxDynamicSharedMemorySize, SMEM_G);
    cudaFuncSetAttribute(gemm_out,    cudaFuncAttributeMaxDynamicSharedMemorySize, SMEM_G);

    // 1) q,k packed hi/lo (permuted), vT (permuted)
    qkv_kernel<<<dim3(16, 16, BATCH), 256>>>(x, Wq, bq, Wk, bk, Wv, bv);

    // 2) logits = q k^T per batch (3xTF32, packed)
    gemm_logits<<<dim3(4, 4, BATCH), 256, SMEM_G>>>(pqp, pkp, pattn);

    // 3) softmax rows (+ tf32 rounding + j-permutation)
    softmax_kernel<<<BATCH * 512, 128>>>();

    // 4) out = attn @ vT per (b,c), single tf32, warp tile 64x64
    gemm_out<<<dim3(4, 4, BATCH * 8), 128, SMEM_G>>>(pattn, pvT, out);
}